// round 1
// baseline (speedup 1.0000x reference)
#include <cuda_runtime.h>
#include <math.h>

#define HH 128
#define WW 128
#define HW (HH*WW)
#define CC 64
#define OO 64
#define BB 4
#define KK 9

// Scratch (allocation-free rule: __device__ globals)
__device__ float4 g_wts[BB*KK*HW];   // per (b,k,pixel): 4 bilinear corner weights * mask
__device__ int4   g_offs[BB*KK*HW];  // per (b,k,pixel): 4 clamped corner offsets into HxW plane
__device__ float  g_wt[KK*CC*OO];    // weight transposed to [k][c][o]

// ---------------- kernel 0: weight transpose [O][C][K] -> [K][C][O] ----------------
__global__ void k_wt_transpose(const float* __restrict__ w) {
    int i = blockIdx.x * 256 + threadIdx.x;
    if (i >= KK*CC*OO) return;
    int k = i >> 12;        // / (CC*OO) = /4096
    int r = i & 4095;
    int c = r >> 6;
    int o = r & 63;
    g_wt[i] = w[(o*CC + c)*KK + k];
}

// ---------------- kernel 1: offset-mask conv + bilinear prep ----------------
// One thread per output pixel; 27 accumulators; weights staged in smem in two
// channel phases (32 channels each) to stay under 48KB static smem.
__global__ __launch_bounds__(256) void k_offset(
        const float* __restrict__ x_extra,
        const float* __restrict__ pre_offset,
        const float* __restrict__ pre_sim,
        const float* __restrict__ w_om,
        const float* __restrict__ b_om) {
    __shared__ float ws[32*9*28];   // [c_local*9+t][27 padded to 28] : 32,256 B
    const int tid = threadIdx.x;
    const int b = blockIdx.z;
    const int h = (blockIdx.y << 4) + (tid >> 4);
    const int w = (blockIdx.x << 4) + (tid & 15);

    float acc[27];
#pragma unroll
    for (int j = 0; j < 27; j++) acc[j] = 0.f;

    const float* xb = x_extra + b*CC*HW;

    for (int phase = 0; phase < 2; ++phase) {
        __syncthreads();
        // stage w_om for channels [phase*32, phase*32+32) as ws[(cl*9+t)*28 + oc]
        for (int idx = tid; idx < 32*9*27; idx += 256) {
            int ct = idx / 27;
            int oc = idx - ct*27;
            int cl = ct / 9;
            int t  = ct - cl*9;
            int c  = (phase << 5) + cl;
            ws[ct*28 + oc] = w_om[(oc*CC + c)*KK + t];
        }
        __syncthreads();

        for (int cl = 0; cl < 32; ++cl) {
            const float* xc = xb + (((phase << 5) + cl) * HW);
            float xv[9];
#pragma unroll
            for (int t = 0; t < 9; t++) {
                int yy = h - 1 + t/3;
                int xx = w - 1 + t%3;
                xv[t] = ((unsigned)yy < HH && (unsigned)xx < WW) ? __ldg(xc + yy*WW + xx) : 0.f;
            }
#pragma unroll
            for (int t = 0; t < 9; t++) {
                const float4* wr = (const float4*)&ws[(cl*9 + t)*28];
                float xt = xv[t];
#pragma unroll
                for (int q = 0; q < 6; q++) {
                    float4 a = wr[q];
                    acc[4*q+0] += xt*a.x; acc[4*q+1] += xt*a.y;
                    acc[4*q+2] += xt*a.z; acc[4*q+3] += xt*a.w;
                }
                float4 a6 = wr[6];
                acc[24] += xt*a6.x; acc[25] += xt*a6.y; acc[26] += xt*a6.z;
            }
        }
    }

    const int pix = h*WW + w;
#pragma unroll
    for (int k = 0; k < 9; k++) {
        float ry = acc[2*k]   + __ldg(b_om + 2*k);
        float rx = acc[2*k+1] + __ldg(b_om + 2*k + 1);
        float rm = acc[18+k]  + __ldg(b_om + 18 + k);
        int gi = (b*KK + k)*HW + pix;
        float poy = __ldg(pre_offset + 2*gi + 1);   // [...,1] -> y
        float pox = __ldg(pre_offset + 2*gi + 0);   // [...,0] -> x
        float ps  = __ldg(pre_sim + gi);

        float py = 10.f*tanhf(ry) + poy + (float)(h - 1) + (float)(k/3);
        float px = 10.f*tanhf(rx) + pox + (float)(w - 1) + (float)(k%3);
        float m  = 1.f / (1.f + expf(-(rm * ps)));

        float fy = floorf(py), fx = floorf(px);
        float dy = py - fy,   dx = px - fx;
        int iy0 = (int)fy, ix0 = (int)fx;
        int iy1 = iy0 + 1, ix1 = ix0 + 1;
        bool vy0 = (unsigned)iy0 < HH, vy1 = (unsigned)iy1 < HH;
        bool vx0 = (unsigned)ix0 < WW, vx1 = (unsigned)ix1 < WW;

        float w00 = (vy0 && vx0) ? (1.f-dy)*(1.f-dx)*m : 0.f;
        float w01 = (vy0 && vx1) ? (1.f-dy)*dx*m       : 0.f;
        float w10 = (vy1 && vx0) ? dy*(1.f-dx)*m       : 0.f;
        float w11 = (vy1 && vx1) ? dy*dx*m             : 0.f;

        int cy0 = min(max(iy0, 0), HH-1), cy1 = min(max(iy1, 0), HH-1);
        int cx0 = min(max(ix0, 0), WW-1), cx1 = min(max(ix1, 0), WW-1);

        g_wts[gi]  = make_float4(w00, w01, w10, w11);
        g_offs[gi] = make_int4(cy0*WW + cx0, cy0*WW + cx1, cy1*WW + cx0, cy1*WW + cx1);
    }
}

// ---------------- kernel 2: gather + per-k 64x64x64 mini-GEMM ----------------
// Block: 256 threads; tile = 64 pixels (16 wide x 4 tall) x 64 output channels.
// Each thread: 4 pixels x 4 out-channels register tile.
__global__ __launch_bounds__(256) void k_main(
        const float* __restrict__ x_main,
        const float* __restrict__ bias,
        float* __restrict__ out) {
    __shared__ float  v_s[CC*64];    // [c][p]  16 KB
    __shared__ float  w_s[CC*OO];    // [c][o]  16 KB
    __shared__ float4 wt_p[64];
    __shared__ int4   off_p[64];

    const int tid = threadIdx.x;
    const int b  = blockIdx.z;
    const int th = blockIdx.y << 2;
    const int tw = blockIdx.x << 4;
    const int tp = tid & 15;    // pixel group (4 pixels each)
    const int to = tid >> 4;    // ochan group (4 chans each)
    const float* xb = x_main + b*CC*HW;

    float4 acc0 = {0,0,0,0}, acc1 = {0,0,0,0}, acc2 = {0,0,0,0}, acc3 = {0,0,0,0};

    for (int k = 0; k < 9; k++) {
        // stage per-pixel bilinear prep for this k
        if (tid < 64) {
            int p = tid;
            int h = th + (p >> 4), w = tw + (p & 15);
            int gi = (b*KK + k)*HW + h*WW + w;
            wt_p[p]  = g_wts[gi];
            off_p[p] = g_offs[gi];
        }
        // stage weight slice [c][o] for this k (coalesced float4)
        {
            const float4* src = (const float4*)(g_wt + k*CC*OO);
            float4* dst = (float4*)w_s;
            for (int i = tid; i < CC*OO/4; i += 256) dst[i] = src[i];
        }
        __syncthreads();

        // gather: 64 pixels x 64 channels of modulated bilinear samples
#pragma unroll
        for (int i = 0; i < 16; i++) {
            int e = (i << 8) + tid;
            int c = e >> 6, p = e & 63;
            float4 wt = wt_p[p];
            int4  of = off_p[p];
            const float* xc = xb + c*HW;
            v_s[(c << 6) + p] = wt.x*__ldg(xc + of.x) + wt.y*__ldg(xc + of.y)
                              + wt.z*__ldg(xc + of.z) + wt.w*__ldg(xc + of.w);
        }
        __syncthreads();

        // mini-GEMM: acc[p][o] += sum_c v[c][p] * w[c][o]
#pragma unroll 8
        for (int c = 0; c < CC; c++) {
            float4 av = *(const float4*)&v_s[(c << 6) + (tp << 2)];
            float4 bv = *(const float4*)&w_s[(c << 6) + (to << 2)];
            acc0.x += av.x*bv.x; acc0.y += av.y*bv.x; acc0.z += av.z*bv.x; acc0.w += av.w*bv.x;
            acc1.x += av.x*bv.y; acc1.y += av.y*bv.y; acc1.z += av.z*bv.y; acc1.w += av.w*bv.y;
            acc2.x += av.x*bv.z; acc2.y += av.y*bv.z; acc2.z += av.z*bv.z; acc2.w += av.w*bv.z;
            acc3.x += av.x*bv.w; acc3.y += av.y*bv.w; acc3.z += av.z*bv.w; acc3.w += av.w*bv.w;
        }
        __syncthreads();
    }

    // epilogue: float4-coalesced stores (4 consecutive pixels per thread)
    int p0 = tp << 2;
    int h = th + (p0 >> 4), w = tw + (p0 & 15);
    float* ob = out + (size_t)b*OO*HW + h*WW + w;
    int o0 = to << 2;
    {
        float bo;
        bo = __ldg(bias + o0 + 0);
        { float4 r = acc0; r.x+=bo; r.y+=bo; r.z+=bo; r.w+=bo; *(float4*)(ob + (o0+0)*HW) = r; }
        bo = __ldg(bias + o0 + 1);
        { float4 r = acc1; r.x+=bo; r.y+=bo; r.z+=bo; r.w+=bo; *(float4*)(ob + (o0+1)*HW) = r; }
        bo = __ldg(bias + o0 + 2);
        { float4 r = acc2; r.x+=bo; r.y+=bo; r.z+=bo; r.w+=bo; *(float4*)(ob + (o0+2)*HW) = r; }
        bo = __ldg(bias + o0 + 3);
        { float4 r = acc3; r.x+=bo; r.y+=bo; r.z+=bo; r.w+=bo; *(float4*)(ob + (o0+3)*HW) = r; }
    }
}

extern "C" void kernel_launch(void* const* d_in, const int* in_sizes, int n_in,
                              void* d_out, int out_size) {
    const float* x_main     = (const float*)d_in[0];
    const float* x_extra    = (const float*)d_in[1];
    const float* pre_offset = (const float*)d_in[2];
    const float* pre_sim    = (const float*)d_in[3];
    const float* weight     = (const float*)d_in[4];
    const float* bias       = (const float*)d_in[5];
    const float* w_om       = (const float*)d_in[6];
    const float* b_om       = (const float*)d_in[7];
    float* out = (float*)d_out;

    k_wt_transpose<<<(KK*CC*OO + 255)/256, 256>>>(weight);

    dim3 g1(WW/16, HH/16, BB);
    k_offset<<<g1, 256>>>(x_extra, pre_offset, pre_sim, w_om, b_om);

    dim3 g2(WW/16, HH/4, BB);
    k_main<<<g2, 256>>>(x_main, bias, out);
}

// round 2
// speedup vs baseline: 1.3759x; 1.3759x over previous
#include <cuda_runtime.h>
#include <math.h>

#define HH 128
#define WW 128
#define HW (HH*WW)
#define CC 64
#define OO 64
#define BB 4
#define KK 9

// Scratch (allocation-free rule: __device__ globals)
__device__ float4 g_wts[BB*KK*HW];      // per (b,k,pixel): 4 bilinear corner weights * mask
__device__ int4   g_offs[BB*KK*HW];     // per (b,k,pixel): 4 clamped corner plane-offsets
__device__ float  g_wt[KK*OO*CC];       // weight transposed to [k][o][c]
__device__ float  g_xm[(size_t)BB*HW*CC]; // x_main pixel-major [b][p][c]

// ---------- packed f32x2 helpers ----------
__device__ __forceinline__ unsigned long long pk2(float lo, float hi) {
    unsigned long long r;
    asm("mov.b64 %0,{%1,%2};" : "=l"(r) : "f"(lo), "f"(hi));
    return r;
}
__device__ __forceinline__ void fma2(unsigned long long& d, unsigned long long a, unsigned long long b) {
    asm("fma.rn.f32x2 %0,%1,%2,%0;" : "+l"(d) : "l"(a), "l"(b));
}
__device__ __forceinline__ float2 up2(unsigned long long v) {
    float2 r;
    asm("mov.b64 {%0,%1},%2;" : "=f"(r.x), "=f"(r.y) : "l"(v));
    return r;
}

// ---------------- kernel 0a: weight transpose [O][C][K] -> [K][O][C] ----------------
__global__ void k_wt_transpose(const float* __restrict__ w) {
    int i = blockIdx.x * 256 + threadIdx.x;
    if (i >= KK*OO*CC) return;
    int k = i >> 12;          // / 4096
    int r = i & 4095;
    int o = r >> 6;
    int c = r & 63;
    g_wt[i] = w[(o*CC + c)*KK + k];
}

// ---------------- kernel 0b: x_main transpose [C][H][W] -> [H][W][C] ----------------
// One block per (b, 64-pixel tile). smem tile transpose, coalesced both ways.
__global__ __launch_bounds__(256) void k_xm_transpose(const float* __restrict__ x) {
    __shared__ float s[64*68];
    const int tid = threadIdx.x;
    const int b = blockIdx.y;
    const int p0 = blockIdx.x << 6;       // 64-pixel tile
    // read: task = (c, p4): float4 along pixels (coalesced)
#pragma unroll
    for (int i = 0; i < 4; i++) {
        int t = (i << 8) + tid;
        int c = t >> 4, p4 = t & 15;
        float4 v = *(const float4*)(x + (((size_t)b*CC + c) << 14) + p0 + (p4 << 2));
        int base = (p4 << 2)*68 + c;
        s[base]       = v.x;
        s[base + 68]  = v.y;
        s[base + 136] = v.z;
        s[base + 204] = v.w;
    }
    __syncthreads();
    // write: task = (p, c4): float4 along channels (coalesced)
#pragma unroll
    for (int i = 0; i < 4; i++) {
        int t = (i << 8) + tid;
        int p = t >> 4, c4 = t & 15;
        float4 v = *(const float4*)&s[p*68 + (c4 << 2)];
        *(float4*)(g_xm + (((size_t)b << 14) + p0 + p)*CC + (c4 << 2)) = v;
    }
}

// ---------------- kernel 1: offset-mask conv + bilinear prep ----------------
// 16x16 pixels per block. x_extra halo tile staged per channel; packed f32x2 acc.
__global__ __launch_bounds__(256) void k_offset(
        const float* __restrict__ x_extra,
        const float* __restrict__ pre_offset,
        const float* __restrict__ pre_sim,
        const float* __restrict__ w_om,
        const float* __restrict__ b_om) {
    __shared__ float ws[32*9*28];   // [c_local*9+t][27 pad 28]
    __shared__ float xt[18*19];     // halo tile, one channel at a time
    const int tid = threadIdx.x;
    const int b = blockIdx.z;
    const int ty = tid >> 4, tx = tid & 15;
    const int h = (blockIdx.y << 4) + ty;
    const int w = (blockIdx.x << 4) + tx;
    const int gy0 = (blockIdx.y << 4) - 1;
    const int gx0 = (blockIdx.x << 4) - 1;

    unsigned long long accP[14];
#pragma unroll
    for (int j = 0; j < 14; j++) accP[j] = 0ULL;

    const float* xb = x_extra + (size_t)b*CC*HW;

    for (int phase = 0; phase < 2; ++phase) {
        __syncthreads();
        for (int idx = tid; idx < 32*9*27; idx += 256) {
            int ct = idx / 27;
            int oc = idx - ct*27;
            int cl = ct / 9;
            int t  = ct - cl*9;
            int c  = (phase << 5) + cl;
            ws[ct*28 + oc] = w_om[(oc*CC + c)*KK + t];
        }
        __syncthreads();

        for (int cl = 0; cl < 32; ++cl) {
            const float* xc = xb + ((size_t)((phase << 5) + cl) << 14);
            __syncthreads();
            for (int idx = tid; idx < 324; idx += 256) {
                int r = idx / 18, cc = idx - r*18;
                int gy = gy0 + r, gx = gx0 + cc;
                xt[r*19 + cc] = ((unsigned)gy < HH && (unsigned)gx < WW)
                                  ? __ldg(xc + gy*WW + gx) : 0.f;
            }
            __syncthreads();
#pragma unroll
            for (int t = 0; t < 9; t++) {
                float xv = xt[(ty + t/3)*19 + tx + t%3];
                unsigned long long x2 = pk2(xv, xv);
                const ulonglong2* wr = (const ulonglong2*)&ws[(cl*9 + t)*28];
#pragma unroll
                for (int q = 0; q < 7; q++) {
                    ulonglong2 wq = wr[q];
                    fma2(accP[2*q],   x2, wq.x);
                    fma2(accP[2*q+1], x2, wq.y);
                }
            }
        }
    }

    float acc[28];
#pragma unroll
    for (int j = 0; j < 14; j++) {
        float2 f = up2(accP[j]);
        acc[2*j] = f.x; acc[2*j+1] = f.y;
    }

    const int pix = h*WW + w;
#pragma unroll
    for (int k = 0; k < 9; k++) {
        float ry = acc[2*k]   + __ldg(b_om + 2*k);
        float rx = acc[2*k+1] + __ldg(b_om + 2*k + 1);
        float rm = acc[18+k]  + __ldg(b_om + 18 + k);
        int gi = (b*KK + k)*HW + pix;
        float poy = __ldg(pre_offset + 2*gi + 1);
        float pox = __ldg(pre_offset + 2*gi + 0);
        float ps  = __ldg(pre_sim + gi);

        float py = 10.f*tanhf(ry) + poy + (float)(h - 1) + (float)(k/3);
        float px = 10.f*tanhf(rx) + pox + (float)(w - 1) + (float)(k%3);
        float m  = 1.f / (1.f + expf(-(rm * ps)));

        float fy = floorf(py), fx = floorf(px);
        float dy = py - fy,   dx = px - fx;
        int iy0 = (int)fy, ix0 = (int)fx;
        int iy1 = iy0 + 1, ix1 = ix0 + 1;
        bool vy0 = (unsigned)iy0 < HH, vy1 = (unsigned)iy1 < HH;
        bool vx0 = (unsigned)ix0 < WW, vx1 = (unsigned)ix1 < WW;

        float w00 = (vy0 && vx0) ? (1.f-dy)*(1.f-dx)*m : 0.f;
        float w01 = (vy0 && vx1) ? (1.f-dy)*dx*m       : 0.f;
        float w10 = (vy1 && vx0) ? dy*(1.f-dx)*m       : 0.f;
        float w11 = (vy1 && vx1) ? dy*dx*m             : 0.f;

        int cy0 = min(max(iy0, 0), HH-1), cy1 = min(max(iy1, 0), HH-1);
        int cx0 = min(max(ix0, 0), WW-1), cx1 = min(max(ix1, 0), WW-1);

        g_wts[gi]  = make_float4(w00, w01, w10, w11);
        g_offs[gi] = make_int4(cy0*WW + cx0, cy0*WW + cx1, cy1*WW + cx0, cy1*WW + cx1);
    }
}

// ---------------- kernel 2: gather (pixel-major) + per-k mini-GEMM (f32x2) ----------------
// Block: 256 threads; tile = 64 pixels (16w x 4h) x 64 ochans.
// Thread: 4 consecutive pixels x 4 ochans, accumulators packed along channel pairs.
__global__ __launch_bounds__(256) void k_main(
        const float* __restrict__ bias,
        float* __restrict__ out) {
    __shared__ float4 v4[64*16];   // v[p][c4], col-swizzled: [p][c4 ^ (p>>2)]
    __shared__ float4 w4[64*16];   // w[o][c4]

    const int tid = threadIdx.x;
    const int b  = blockIdx.z;
    const int th = blockIdx.y << 2;
    const int tw = blockIdx.x << 4;
    const int tp = tid & 15;
    const int to = tid >> 4;
    const float* xb = g_xm + ((size_t)b << 20);   // b*HW*CC

    unsigned long long acc[16];
#pragma unroll
    for (int j = 0; j < 16; j++) acc[j] = 0ULL;

    for (int k = 0; k < 9; k++) {
        // stage weight slice [o][c] for this k (coalesced float4)
        {
            const float4* src = (const float4*)(g_wt + (k << 12));
#pragma unroll
            for (int i = 0; i < 4; i++) w4[(i << 8) + tid] = src[(i << 8) + tid];
        }
        // gather: task = (p, c4); 16 threads share a pixel -> broadcast wts/offs
#pragma unroll
        for (int i = 0; i < 4; i++) {
            int t = (i << 8) + tid;
            int c4 = t & 15, p = t >> 4;
            int h = th + (p >> 4), w = tw + (p & 15);
            int gi = ((b*KK + k) << 14) + h*WW + w;
            float4 wt = __ldg(&g_wts[gi]);
            int4   of = __ldg(&g_offs[gi]);
            int cc = c4 << 2;
            float4 A = *(const float4*)(xb + ((size_t)of.x << 6) + cc);
            float4 Bv = *(const float4*)(xb + ((size_t)of.y << 6) + cc);
            float4 Cv = *(const float4*)(xb + ((size_t)of.z << 6) + cc);
            float4 D = *(const float4*)(xb + ((size_t)of.w << 6) + cc);
            float4 val;
            val.x = wt.x*A.x + wt.y*Bv.x + wt.z*Cv.x + wt.w*D.x;
            val.y = wt.x*A.y + wt.y*Bv.y + wt.z*Cv.y + wt.w*D.y;
            val.z = wt.x*A.z + wt.y*Bv.z + wt.z*Cv.z + wt.w*D.z;
            val.w = wt.x*A.w + wt.y*Bv.w + wt.z*Cv.w + wt.w*D.w;
            v4[(p << 4) + (c4 ^ (p >> 2))] = val;
        }
        __syncthreads();

        // mini-GEMM: acc[p][o] += sum_c v[p][c] * w[o][c], packed along c-pairs
#pragma unroll
        for (int c4 = 0; c4 < 16; c4++) {
            int sc = c4 ^ tp;
            float4 a0 = v4[((tp << 2) + 0)*16 + sc];
            float4 a1 = v4[((tp << 2) + 1)*16 + sc];
            float4 a2 = v4[((tp << 2) + 2)*16 + sc];
            float4 a3 = v4[((tp << 2) + 3)*16 + sc];
            float4 b0 = w4[((to << 2) + 0)*16 + c4];
            float4 b1 = w4[((to << 2) + 1)*16 + c4];
            float4 b2 = w4[((to << 2) + 2)*16 + c4];
            float4 b3 = w4[((to << 2) + 3)*16 + c4];
            ulonglong2 au0 = *(ulonglong2*)&a0, au1 = *(ulonglong2*)&a1;
            ulonglong2 au2 = *(ulonglong2*)&a2, au3 = *(ulonglong2*)&a3;
            ulonglong2 bu0 = *(ulonglong2*)&b0, bu1 = *(ulonglong2*)&b1;
            ulonglong2 bu2 = *(ulonglong2*)&b2, bu3 = *(ulonglong2*)&b3;
            fma2(acc[0],  au0.x, bu0.x); fma2(acc[0],  au0.y, bu0.y);
            fma2(acc[1],  au0.x, bu1.x); fma2(acc[1],  au0.y, bu1.y);
            fma2(acc[2],  au0.x, bu2.x); fma2(acc[2],  au0.y, bu2.y);
            fma2(acc[3],  au0.x, bu3.x); fma2(acc[3],  au0.y, bu3.y);
            fma2(acc[4],  au1.x, bu0.x); fma2(acc[4],  au1.y, bu0.y);
            fma2(acc[5],  au1.x, bu1.x); fma2(acc[5],  au1.y, bu1.y);
            fma2(acc[6],  au1.x, bu2.x); fma2(acc[6],  au1.y, bu2.y);
            fma2(acc[7],  au1.x, bu3.x); fma2(acc[7],  au1.y, bu3.y);
            fma2(acc[8],  au2.x, bu0.x); fma2(acc[8],  au2.y, bu0.y);
            fma2(acc[9],  au2.x, bu1.x); fma2(acc[9],  au2.y, bu1.y);
            fma2(acc[10], au2.x, bu2.x); fma2(acc[10], au2.y, bu2.y);
            fma2(acc[11], au2.x, bu3.x); fma2(acc[11], au2.y, bu3.y);
            fma2(acc[12], au3.x, bu0.x); fma2(acc[12], au3.y, bu0.y);
            fma2(acc[13], au3.x, bu1.x); fma2(acc[13], au3.y, bu1.y);
            fma2(acc[14], au3.x, bu2.x); fma2(acc[14], au3.y, bu2.y);
            fma2(acc[15], au3.x, bu3.x); fma2(acc[15], au3.y, bu3.y);
        }
        __syncthreads();
    }

    // epilogue: 4 consecutive pixels per thread -> float4 stores
    int p0 = tp << 2;
    int h = th + (p0 >> 4), w = tw + (p0 & 15);
    float* ob = out + ((size_t)b*OO << 14) + h*WW + w;
#pragma unroll
    for (int jj = 0; jj < 4; jj++) {
        int o = (to << 2) + jj;
        float bo = __ldg(bias + o);
        float2 s0 = up2(acc[0*4 + jj]);
        float2 s1 = up2(acc[1*4 + jj]);
        float2 s2 = up2(acc[2*4 + jj]);
        float2 s3 = up2(acc[3*4 + jj]);
        float4 r = make_float4(s0.x + s0.y + bo, s1.x + s1.y + bo,
                               s2.x + s2.y + bo, s3.x + s3.y + bo);
        *(float4*)(ob + ((size_t)o << 14)) = r;
    }
}

extern "C" void kernel_launch(void* const* d_in, const int* in_sizes, int n_in,
                              void* d_out, int out_size) {
    const float* x_main     = (const float*)d_in[0];
    const float* x_extra    = (const float*)d_in[1];
    const float* pre_offset = (const float*)d_in[2];
    const float* pre_sim    = (const float*)d_in[3];
    const float* weight     = (const float*)d_in[4];
    const float* bias       = (const float*)d_in[5];
    const float* w_om       = (const float*)d_in[6];
    const float* b_om       = (const float*)d_in[7];
    float* out = (float*)d_out;

    k_wt_transpose<<<(KK*OO*CC + 255)/256, 256>>>(weight);

    dim3 gt(HW/64, BB);
    k_xm_transpose<<<gt, 256>>>(x_main);

    dim3 g1(WW/16, HH/16, BB);
    k_offset<<<g1, 256>>>(x_extra, pre_offset, pre_sim, w_om, b_om);

    dim3 g2(WW/16, HH/4, BB);
    k_main<<<g2, 256>>>(bias, out);
}